// round 4
// baseline (speedup 1.0000x reference)
#include <cuda_runtime.h>

#define IN_F 256
#define NHEAD 8
#define OUT_F 64
#define TMAX 8
#define MAXN 100000

// Scratch (static __device__ — no allocations allowed)
__device__ float g_A[IN_F * 16];       // [i][0..7]=A_l, [i][8..15]=A_r
__device__ float g_ee[TMAX * NHEAD];   // per-etype logit table
__device__ float g_el[MAXN * NHEAD];
__device__ float g_er[MAXN * NHEAD];
__device__ float g_s[MAXN * NHEAD];    // softmax denominator -> reciprocal in-place

// ---------------------------------------------------------------------------
// K1: fold attn_l/attn_r into W_fc:  A_l[i,h] = sum_o W_fc[i, h*64+o]*attn_l[h,o]
// grid = 256 (i), block = 256 (warp h computes head h)
// ---------------------------------------------------------------------------
__global__ void build_A(const float* __restrict__ W_fc,
                        const float* __restrict__ attn_l,
                        const float* __restrict__ attn_r) {
    int i = blockIdx.x;
    int h = threadIdx.x >> 5;
    int lane = threadIdx.x & 31;
    const float* wrow = W_fc + (size_t)i * (NHEAD * OUT_F) + h * OUT_F;
    const float* al = attn_l + h * OUT_F;
    const float* ar = attn_r + h * OUT_F;
    float sl = wrow[lane] * al[lane] + wrow[lane + 32] * al[lane + 32];
    float sr = wrow[lane] * ar[lane] + wrow[lane + 32] * ar[lane + 32];
#pragma unroll
    for (int o = 16; o; o >>= 1) {
        sl += __shfl_xor_sync(0xFFFFFFFFu, sl, o);
        sr += __shfl_xor_sync(0xFFFFFFFFu, sr, o);
    }
    if (lane == 0) {
        g_A[i * 16 + h] = sl;
        g_A[i * 16 + 8 + h] = sr;
    }
}

// ---------------------------------------------------------------------------
// K2: edge-type logit table:
//   ee[t,h] = sum_f (edge_emb[t,:] @ W_e[:, h*64+f]) * attn_e[h,f]
// grid = T (t), block = 256 (warp h)
// ---------------------------------------------------------------------------
__global__ void build_ee(const float* __restrict__ edge_emb,
                         const float* __restrict__ W_e,
                         const float* __restrict__ attn_e) {
    int t = blockIdx.x;
    int h = threadIdx.x >> 5;
    int lane = threadIdx.x & 31;
    float acc = 0.0f;
#pragma unroll
    for (int j = 0; j < 2; j++) {
        int f = lane + j * 32;
        float proj = 0.0f;
#pragma unroll 8
        for (int g = 0; g < 64; g++)
            proj += edge_emb[t * 64 + g] * W_e[(size_t)g * (NHEAD * 64) + h * 64 + f];
        acc += proj * attn_e[h * 64 + f];
    }
#pragma unroll
    for (int o = 16; o; o >>= 1)
        acc += __shfl_xor_sync(0xFFFFFFFFu, acc, o);
    if (lane == 0) g_ee[t * NHEAD + h] = acc;
}

// ---------------------------------------------------------------------------
// K3: node projection el/er = feat @ [A_l | A_r]   ([N,256] @ [256,16])
// block = 128 (4 warps); each warp owns 32 nodes (1 per lane), A in smem with
// broadcast reads, feat staged through a swizzled smem tile (conflict-free).
// ---------------------------------------------------------------------------
__global__ void __launch_bounds__(128) node_proj(const float* __restrict__ feat, int N) {
    __shared__ float sA[IN_F * 16];     // 16 KB
    __shared__ float sF[4][32][32];     // 16 KB, XOR-swizzled
    int tid = threadIdx.x;
    for (int i = tid; i < IN_F * 16; i += 128) sA[i] = g_A[i];
    int w = tid >> 5, lane = tid & 31;
    int nodeBase = blockIdx.x * 128 + w * 32;
    int myNode = nodeBase + lane;
    float accl[8] = {0, 0, 0, 0, 0, 0, 0, 0};
    float accr[8] = {0, 0, 0, 0, 0, 0, 0, 0};
    __syncthreads();

    for (int kc = 0; kc < IN_F; kc += 32) {
#pragma unroll
        for (int r = 0; r < 32; r++) {
            int row = nodeBase + r;
            if (row > N - 1) row = N - 1;
            sF[w][r][(lane + r) & 31] = feat[(size_t)row * IN_F + kc + lane];
        }
        __syncwarp();
#pragma unroll 8
        for (int k = 0; k < 32; k++) {
            float f = sF[w][lane][(k + lane) & 31];
            const float4* ap = (const float4*)&sA[(kc + k) * 16];
            float4 a0 = ap[0], a1 = ap[1], a2 = ap[2], a3 = ap[3];
            accl[0] += f * a0.x; accl[1] += f * a0.y; accl[2] += f * a0.z; accl[3] += f * a0.w;
            accl[4] += f * a1.x; accl[5] += f * a1.y; accl[6] += f * a1.z; accl[7] += f * a1.w;
            accr[0] += f * a2.x; accr[1] += f * a2.y; accr[2] += f * a2.z; accr[3] += f * a2.w;
            accr[4] += f * a3.x; accr[5] += f * a3.y; accr[6] += f * a3.z; accr[7] += f * a3.w;
        }
        __syncwarp();
    }
    if (myNode < N) {
        float4* pl = (float4*)&g_el[myNode * 8];
        pl[0] = make_float4(accl[0], accl[1], accl[2], accl[3]);
        pl[1] = make_float4(accl[4], accl[5], accl[6], accl[7]);
        float4* pr = (float4*)&g_er[myNode * 8];
        pr[0] = make_float4(accr[0], accr[1], accr[2], accr[3]);
        pr[1] = make_float4(accr[4], accr[5], accr[6], accr[7]);
    }
}

// ---------------------------------------------------------------------------
// K4: zero the denominator accumulator
// ---------------------------------------------------------------------------
__global__ void zero_s(int nh) {
    int i = blockIdx.x * blockDim.x + threadIdx.x;
    if (i < nh) g_s[i] = 0.0f;
}

// ---------------------------------------------------------------------------
// K5: per-edge ex = exp(relu(el[src]+er[dst]+ee[etype])), accumulate s[dst]
// with vectorized red.global.add.v4.f32 (2 atomics per edge instead of 8).
// Max-shift is dropped: softmax is shift-invariant and e in [0, ~2].
// ---------------------------------------------------------------------------
__global__ void __launch_bounds__(256) edge_expsum(const int* __restrict__ et,
                                                   const int* __restrict__ src,
                                                   const int* __restrict__ dst,
                                                   int E) {
    __shared__ float see[TMAX * NHEAD];
    if (threadIdx.x < TMAX * NHEAD) see[threadIdx.x] = g_ee[threadIdx.x];
    __syncthreads();
    int e = blockIdx.x * blockDim.x + threadIdx.x;
    if (e >= E) return;
    int s = __ldg(&src[e]);
    int d = __ldg(&dst[e]);
    int t = __ldg(&et[e]);
    const float4* pl = (const float4*)(g_el + (size_t)s * 8);
    const float4* pr = (const float4*)(g_er + (size_t)d * 8);
    float4 l0 = __ldg(pl), l1 = __ldg(pl + 1);
    float4 r0 = __ldg(pr), r1 = __ldg(pr + 1);
    float4 e0 = *(const float4*)&see[t * 8];
    float4 e1 = *(const float4*)&see[t * 8 + 4];
    float x0 = __expf(fmaxf(l0.x + r0.x + e0.x, 0.0f));
    float x1 = __expf(fmaxf(l0.y + r0.y + e0.y, 0.0f));
    float x2 = __expf(fmaxf(l0.z + r0.z + e0.z, 0.0f));
    float x3 = __expf(fmaxf(l0.w + r0.w + e0.w, 0.0f));
    float x4 = __expf(fmaxf(l1.x + r1.x + e1.x, 0.0f));
    float x5 = __expf(fmaxf(l1.y + r1.y + e1.y, 0.0f));
    float x6 = __expf(fmaxf(l1.z + r1.z + e1.z, 0.0f));
    float x7 = __expf(fmaxf(l1.w + r1.w + e1.w, 0.0f));
    float* sp = g_s + (size_t)d * 8;
    asm volatile("red.global.add.v4.f32 [%0], {%1,%2,%3,%4};"
                 :: "l"(sp), "f"(x0), "f"(x1), "f"(x2), "f"(x3) : "memory");
    asm volatile("red.global.add.v4.f32 [%0], {%1,%2,%3,%4};"
                 :: "l"(sp + 4), "f"(x4), "f"(x5), "f"(x6), "f"(x7) : "memory");
}

// ---------------------------------------------------------------------------
// K6: s -> 1/s (per node-head); isolated nodes give inf but are never read.
// ---------------------------------------------------------------------------
__global__ void recip_s(int nh) {
    int i = blockIdx.x * blockDim.x + threadIdx.x;
    if (i < nh) g_s[i] = __frcp_rn(g_s[i]);
}

// ---------------------------------------------------------------------------
// K7: recompute ex (gathers are L2-resident) and write out = ex * rinv[dst].
// Avoids a 204 MB d_out round-trip vs. storing ex in K5.
// ---------------------------------------------------------------------------
__global__ void __launch_bounds__(256) edge_out(const int* __restrict__ et,
                                                const int* __restrict__ src,
                                                const int* __restrict__ dst,
                                                float* __restrict__ out,
                                                int E) {
    __shared__ float see[TMAX * NHEAD];
    if (threadIdx.x < TMAX * NHEAD) see[threadIdx.x] = g_ee[threadIdx.x];
    __syncthreads();
    int e = blockIdx.x * blockDim.x + threadIdx.x;
    if (e >= E) return;
    int s = __ldg(&src[e]);
    int d = __ldg(&dst[e]);
    int t = __ldg(&et[e]);
    const float4* pl = (const float4*)(g_el + (size_t)s * 8);
    const float4* pr = (const float4*)(g_er + (size_t)d * 8);
    const float4* pv = (const float4*)(g_s + (size_t)d * 8);
    float4 l0 = __ldg(pl), l1 = __ldg(pl + 1);
    float4 r0 = __ldg(pr), r1 = __ldg(pr + 1);
    float4 v0 = __ldg(pv), v1 = __ldg(pv + 1);
    float4 e0 = *(const float4*)&see[t * 8];
    float4 e1 = *(const float4*)&see[t * 8 + 4];
    float4 o0, o1;
    o0.x = __expf(fmaxf(l0.x + r0.x + e0.x, 0.0f)) * v0.x;
    o0.y = __expf(fmaxf(l0.y + r0.y + e0.y, 0.0f)) * v0.y;
    o0.z = __expf(fmaxf(l0.z + r0.z + e0.z, 0.0f)) * v0.z;
    o0.w = __expf(fmaxf(l0.w + r0.w + e0.w, 0.0f)) * v0.w;
    o1.x = __expf(fmaxf(l1.x + r1.x + e1.x, 0.0f)) * v1.x;
    o1.y = __expf(fmaxf(l1.y + r1.y + e1.y, 0.0f)) * v1.y;
    o1.z = __expf(fmaxf(l1.z + r1.z + e1.z, 0.0f)) * v1.z;
    o1.w = __expf(fmaxf(l1.w + r1.w + e1.w, 0.0f)) * v1.w;
    float4* po = (float4*)(out + (size_t)e * 8);
    po[0] = o0;
    po[1] = o1;
}

// ---------------------------------------------------------------------------
extern "C" void kernel_launch(void* const* d_in, const int* in_sizes, int n_in,
                              void* d_out, int out_size) {
    const float* feat     = (const float*)d_in[0];
    const int*   etype    = (const int*)  d_in[1];
    const int*   src      = (const int*)  d_in[2];
    const int*   dst      = (const int*)  d_in[3];
    const float* W_fc     = (const float*)d_in[4];
    const float* edge_emb = (const float*)d_in[5];
    const float* W_e      = (const float*)d_in[6];
    const float* attn_l   = (const float*)d_in[7];
    const float* attn_r   = (const float*)d_in[8];
    const float* attn_e   = (const float*)d_in[9];
    float* out = (float*)d_out;

    int N = in_sizes[0] / IN_F;
    int E = in_sizes[1];
    int nh = N * NHEAD;

    build_A<<<IN_F, 256>>>(W_fc, attn_l, attn_r);
    build_ee<<<TMAX, 256>>>(edge_emb, W_e, attn_e);
    node_proj<<<(N + 127) / 128, 128>>>(feat, N);
    zero_s<<<(nh + 255) / 256, 256>>>(nh);
    edge_expsum<<<(E + 255) / 256, 256>>>(etype, src, dst, E);
    recip_s<<<(nh + 255) / 256, 256>>>(nh);
    edge_out<<<(E + 255) / 256, 256>>>(etype, src, dst, out, E);
}

// round 5
// speedup vs baseline: 1.0694x; 1.0694x over previous
#include <cuda_runtime.h>

#define IN_F 256
#define NHEAD 8
#define OUT_F 64
#define TMAX 8
#define MAXN 100000

// Scratch (static __device__ — no allocations allowed)
__device__ float g_A[IN_F * 16];        // [i][0..7]=A_l, [i][8..15]=A_r
__device__ float g_ee[TMAX * NHEAD];    // per-etype logit table
__device__ float g_el[MAXN * NHEAD];    // el, 32B records
// Packed per-node record, 64B: [er0 er1 s0 s1 | er2 er3 s2 s3 | er4 er5 s4 s5 | er6 er7 s6 s7]
// One float4 gather in edge_out fetches both the er pair and the s pair.
__device__ float g_erp[MAXN * 16];

// ---------------------------------------------------------------------------
// K1: setup — fold attn_l/attn_r into W_fc (blocks 0..255, one per input row i)
//     and build the TxH edge-type logit table (blocks 256..263, one per t).
// ---------------------------------------------------------------------------
__global__ void setup(const float* __restrict__ W_fc,
                      const float* __restrict__ attn_l,
                      const float* __restrict__ attn_r,
                      const float* __restrict__ edge_emb,
                      const float* __restrict__ W_e,
                      const float* __restrict__ attn_e) {
    int h = threadIdx.x >> 5;
    int lane = threadIdx.x & 31;
    if (blockIdx.x < IN_F) {
        int i = blockIdx.x;
        const float* wrow = W_fc + (size_t)i * (NHEAD * OUT_F) + h * OUT_F;
        const float* al = attn_l + h * OUT_F;
        const float* ar = attn_r + h * OUT_F;
        float sl = wrow[lane] * al[lane] + wrow[lane + 32] * al[lane + 32];
        float sr = wrow[lane] * ar[lane] + wrow[lane + 32] * ar[lane + 32];
#pragma unroll
        for (int o = 16; o; o >>= 1) {
            sl += __shfl_xor_sync(0xFFFFFFFFu, sl, o);
            sr += __shfl_xor_sync(0xFFFFFFFFu, sr, o);
        }
        if (lane == 0) {
            g_A[i * 16 + h] = sl;
            g_A[i * 16 + 8 + h] = sr;
        }
    } else {
        int t = blockIdx.x - IN_F;
        float acc = 0.0f;
#pragma unroll
        for (int j = 0; j < 2; j++) {
            int f = lane + j * 32;
            float proj = 0.0f;
#pragma unroll 8
            for (int g = 0; g < 64; g++)
                proj += edge_emb[t * 64 + g] * W_e[(size_t)g * (NHEAD * 64) + h * 64 + f];
            acc += proj * attn_e[h * 64 + f];
        }
#pragma unroll
        for (int o = 16; o; o >>= 1)
            acc += __shfl_xor_sync(0xFFFFFFFFu, acc, o);
        if (lane == 0) g_ee[t * NHEAD + h] = acc;
    }
}

// ---------------------------------------------------------------------------
// K2: node projection el/er = feat @ [A_l | A_r]   ([N,256] @ [256,16]).
// Writes el (32B record) and the packed er+s(=0) record (64B), which also
// zeroes the softmax accumulator — no separate memset kernel.
// ---------------------------------------------------------------------------
__global__ void __launch_bounds__(128) node_proj(const float* __restrict__ feat, int N) {
    __shared__ float sA[IN_F * 16];     // 16 KB
    __shared__ float sF[4][32][32];     // 16 KB, XOR-swizzled
    int tid = threadIdx.x;
    for (int i = tid; i < IN_F * 16; i += 128) sA[i] = g_A[i];
    int w = tid >> 5, lane = tid & 31;
    int nodeBase = blockIdx.x * 128 + w * 32;
    int myNode = nodeBase + lane;
    float accl[8] = {0, 0, 0, 0, 0, 0, 0, 0};
    float accr[8] = {0, 0, 0, 0, 0, 0, 0, 0};
    __syncthreads();

    for (int kc = 0; kc < IN_F; kc += 32) {
#pragma unroll
        for (int r = 0; r < 32; r++) {
            int row = nodeBase + r;
            if (row > N - 1) row = N - 1;
            sF[w][r][(lane + r) & 31] = feat[(size_t)row * IN_F + kc + lane];
        }
        __syncwarp();
#pragma unroll 8
        for (int k = 0; k < 32; k++) {
            float f = sF[w][lane][(k + lane) & 31];
            const float4* ap = (const float4*)&sA[(kc + k) * 16];
            float4 a0 = ap[0], a1 = ap[1], a2 = ap[2], a3 = ap[3];
            accl[0] += f * a0.x; accl[1] += f * a0.y; accl[2] += f * a0.z; accl[3] += f * a0.w;
            accl[4] += f * a1.x; accl[5] += f * a1.y; accl[6] += f * a1.z; accl[7] += f * a1.w;
            accr[0] += f * a2.x; accr[1] += f * a2.y; accr[2] += f * a2.z; accr[3] += f * a2.w;
            accr[4] += f * a3.x; accr[5] += f * a3.y; accr[6] += f * a3.z; accr[7] += f * a3.w;
        }
        __syncwarp();
    }
    if (myNode < N) {
        float4* pl = (float4*)&g_el[myNode * 8];
        pl[0] = make_float4(accl[0], accl[1], accl[2], accl[3]);
        pl[1] = make_float4(accl[4], accl[5], accl[6], accl[7]);
        float4* pe = (float4*)&g_erp[(size_t)myNode * 16];
        pe[0] = make_float4(accr[0], accr[1], 0.0f, 0.0f);
        pe[1] = make_float4(accr[2], accr[3], 0.0f, 0.0f);
        pe[2] = make_float4(accr[4], accr[5], 0.0f, 0.0f);
        pe[3] = make_float4(accr[6], accr[7], 0.0f, 0.0f);
    }
}

// ---------------------------------------------------------------------------
// K3: 4 threads per edge, 2 heads per thread. One float2 gather per table per
// edge (wavefronts = lines touched, the minimum). Accumulate s into the packed
// record with red.global.add.v2.f32. Max-shift dropped (softmax shift-
// invariant; e = relu(..) in [0,~2], no overflow risk).
// ---------------------------------------------------------------------------
__global__ void __launch_bounds__(256) edge_expsum(const int* __restrict__ et,
                                                   const int* __restrict__ src,
                                                   const int* __restrict__ dst,
                                                   int E) {
    __shared__ float see[TMAX * NHEAD];
    if (threadIdx.x < TMAX * NHEAD) see[threadIdx.x] = g_ee[threadIdx.x];
    __syncthreads();
    int idx = blockIdx.x * 256 + threadIdx.x;
    int e = idx >> 2;
    int sub = idx & 3;
    if (e >= E) return;
    int s = src[e];
    int d = dst[e];
    int t = et[e];
    float2 l = *(const float2*)(g_el + (size_t)s * 8 + sub * 2);
    float2 r = *(const float2*)(g_erp + (size_t)d * 16 + sub * 4);
    float2 b = *(const float2*)(see + t * 8 + sub * 2);
    float x0 = __expf(fmaxf(l.x + r.x + b.x, 0.0f));
    float x1 = __expf(fmaxf(l.y + r.y + b.y, 0.0f));
    float* sp = g_erp + (size_t)d * 16 + sub * 4 + 2;
    asm volatile("red.global.add.v2.f32 [%0], {%1,%2};"
                 :: "l"(sp), "f"(x0), "f"(x1) : "memory");
}

// ---------------------------------------------------------------------------
// K4: recompute ex (el/erp tables are L2-resident) and write out = ex / s[dst].
// The packed record gives er pair + s pair in ONE float4 gather; the divide
// replaces the former recip_s kernel (MUFU is idle here anyway).
// ---------------------------------------------------------------------------
__global__ void __launch_bounds__(256) edge_out(const int* __restrict__ et,
                                                const int* __restrict__ src,
                                                const int* __restrict__ dst,
                                                float* __restrict__ out,
                                                int E) {
    __shared__ float see[TMAX * NHEAD];
    if (threadIdx.x < TMAX * NHEAD) see[threadIdx.x] = g_ee[threadIdx.x];
    __syncthreads();
    int idx = blockIdx.x * 256 + threadIdx.x;
    int e = idx >> 2;
    int sub = idx & 3;
    if (e >= E) return;
    int s = src[e];
    int d = dst[e];
    int t = et[e];
    float2 l = *(const float2*)(g_el + (size_t)s * 8 + sub * 2);
    float4 c = *(const float4*)(g_erp + (size_t)d * 16 + sub * 4); // er0 er1 s0 s1
    float2 b = *(const float2*)(see + t * 8 + sub * 2);
    float x0 = __expf(fmaxf(l.x + c.x + b.x, 0.0f));
    float x1 = __expf(fmaxf(l.y + c.y + b.y, 0.0f));
    float2 o;
    o.x = __fdividef(x0, c.z);
    o.y = __fdividef(x1, c.w);
    *(float2*)(out + (size_t)e * 8 + sub * 2) = o;
}

// ---------------------------------------------------------------------------
extern "C" void kernel_launch(void* const* d_in, const int* in_sizes, int n_in,
                              void* d_out, int out_size) {
    const float* feat     = (const float*)d_in[0];
    const int*   etype    = (const int*)  d_in[1];
    const int*   src      = (const int*)  d_in[2];
    const int*   dst      = (const int*)  d_in[3];
    const float* W_fc     = (const float*)d_in[4];
    const float* edge_emb = (const float*)d_in[5];
    const float* W_e      = (const float*)d_in[6];
    const float* attn_l   = (const float*)d_in[7];
    const float* attn_r   = (const float*)d_in[8];
    const float* attn_e   = (const float*)d_in[9];
    float* out = (float*)d_out;

    int N = in_sizes[0] / IN_F;
    int E = in_sizes[1];

    setup<<<IN_F + TMAX, 256>>>(W_fc, attn_l, attn_r, edge_emb, W_e, attn_e);
    node_proj<<<(N + 127) / 128, 128>>>(feat, N);
    int ethreads = E * 4;
    edge_expsum<<<(ethreads + 255) / 256, 256>>>(etype, src, dst, E);
    edge_out<<<(ethreads + 255) / 256, 256>>>(etype, src, dst, out, E);
}